// round 1
// baseline (speedup 1.0000x reference)
#include <cuda_runtime.h>
#include <cuda_fp16.h>
#include <mma.h>

using namespace nvcuda;

#define HIDDEN   512
#define HEADS    8
#define HEAD_DIM 64
#define BATCH    4096
#define SEQ      16
#define NTOK     (BATCH * SEQ)   // 65536
#define NQKV     (3 * HIDDEN)    // 1536

// ---- scratch (no allocs allowed; device globals are the sanctioned path) ----
__device__ __half g_xh  [(size_t)NTOK * HIDDEN];   // 64 MiB  fp16 input
__device__ __half g_wq  [(size_t)NQKV * HIDDEN];   // 1.5 MiB fp16 w_qkv
__device__ __half g_wo  [(size_t)HIDDEN * HIDDEN]; // 0.5 MiB fp16 w_o
__device__ float  g_qkv [(size_t)NTOK * NQKV];     // 384 MiB fp32 qkv
__device__ __half g_attn[(size_t)NTOK * HIDDEN];   // 64 MiB  fp16 attn out

// ---------------------------------------------------------------------------
// fp32 -> fp16 converters (n always multiple of 4)
// ---------------------------------------------------------------------------
__device__ __forceinline__ void f2h_body(const float* __restrict__ in,
                                         __half* __restrict__ out, int n) {
    int i = 4 * (blockIdx.x * blockDim.x + threadIdx.x);
    if (i < n) {
        float4 v = *reinterpret_cast<const float4*>(in + i);
        *reinterpret_cast<__half2*>(out + i)     = __floats2half2_rn(v.x, v.y);
        *reinterpret_cast<__half2*>(out + i + 2) = __floats2half2_rn(v.z, v.w);
    }
}

__global__ void f2h_x_kernel (const float* __restrict__ in) { f2h_body(in, g_xh, NTOK * HIDDEN); }
__global__ void f2h_wq_kernel(const float* __restrict__ in) { f2h_body(in, g_wq, NQKV * HIDDEN); }
__global__ void f2h_wo_kernel(const float* __restrict__ in) { f2h_body(in, g_wo, HIDDEN * HIDDEN); }

// ---------------------------------------------------------------------------
// GEMM: C[M,N] = A[M,K] * B[N,K]^T   (A,B fp16 K-contiguous; C fp32)
// Block tile 128x128x32, 256 threads, 8 warps -> warp tile 32x64.
// M,N,K all exact multiples of the tile sizes here, so no predication.
// ---------------------------------------------------------------------------
__device__ __forceinline__ void gemm_body(const __half* __restrict__ A,
                                          const __half* __restrict__ B,
                                          float* __restrict__ C,
                                          int N, int K) {
    constexpr int BM = 128, BN = 128, BK = 32, LDS = BK + 8; // pad->40 (16B-mult rows)
    __shared__ __align__(16) __half As[BM * LDS];
    __shared__ __align__(16) __half Bs[BN * LDS];

    const int bm  = blockIdx.y * BM;
    const int bn  = blockIdx.x * BN;
    const int tid = threadIdx.x;
    const int warp = tid >> 5;
    const int wm = (warp & 3) * 32;   // warp row offset in tile
    const int wn = (warp >> 2) * 64;  // warp col offset in tile

    wmma::fragment<wmma::accumulator, 16, 16, 16, float> acc[2][4];
    #pragma unroll
    for (int i = 0; i < 2; i++)
        #pragma unroll
        for (int j = 0; j < 4; j++) wmma::fill_fragment(acc[i][j], 0.0f);

    for (int kt = 0; kt < K; kt += BK) {
        // Stage 128x32 halves of A and B: 512 int4 each, 2 per thread.
        #pragma unroll
        for (int l = 0; l < 2; l++) {
            int v  = tid + l * 256;
            int r  = v >> 2;
            int c8 = (v & 3) * 8;
            *reinterpret_cast<int4*>(&As[r * LDS + c8]) =
                *reinterpret_cast<const int4*>(&A[(size_t)(bm + r) * K + kt + c8]);
            *reinterpret_cast<int4*>(&Bs[r * LDS + c8]) =
                *reinterpret_cast<const int4*>(&B[(size_t)(bn + r) * K + kt + c8]);
        }
        __syncthreads();

        #pragma unroll
        for (int kk = 0; kk < BK; kk += 16) {
            wmma::fragment<wmma::matrix_a, 16, 16, 16, __half, wmma::row_major> af[2];
            wmma::fragment<wmma::matrix_b, 16, 16, 16, __half, wmma::col_major> bf[4];
            #pragma unroll
            for (int i = 0; i < 2; i++)
                wmma::load_matrix_sync(af[i], &As[(wm + i * 16) * LDS + kk], LDS);
            #pragma unroll
            for (int j = 0; j < 4; j++)
                wmma::load_matrix_sync(bf[j], &Bs[(wn + j * 16) * LDS + kk], LDS);
            #pragma unroll
            for (int i = 0; i < 2; i++)
                #pragma unroll
                for (int j = 0; j < 4; j++)
                    wmma::mma_sync(acc[i][j], af[i], bf[j], acc[i][j]);
        }
        __syncthreads();
    }

    #pragma unroll
    for (int i = 0; i < 2; i++)
        #pragma unroll
        for (int j = 0; j < 4; j++)
            wmma::store_matrix_sync(&C[(size_t)(bm + wm + i * 16) * N + bn + wn + j * 16],
                                    acc[i][j], N, wmma::mem_row_major);
}

__global__ __launch_bounds__(256) void gemm_qkv_kernel() {
    gemm_body(g_xh, g_wq, g_qkv, NQKV, HIDDEN);
}
__global__ __launch_bounds__(256) void gemm_out_kernel(float* __restrict__ C) {
    gemm_body(g_attn, g_wo, C, HIDDEN, HIDDEN);
}

// ---------------------------------------------------------------------------
// Attention: one block per (batch, head). 16x64 q/k/v tiles, exact fp32
// softmax over 16 keys, output written fp16 into [token, h*64+d] layout.
// ---------------------------------------------------------------------------
__global__ __launch_bounds__(128) void attn_kernel() {
    const int b = blockIdx.x >> 3;
    const int h = blockIdx.x & 7;
    const size_t base = (size_t)b * SEQ;
    const int tid = threadIdx.x;

    __shared__ float sq[SEQ][68], sk[SEQ][68], sv[SEQ][68]; // pad 68 vs bank conflicts
    __shared__ float sp[SEQ][SEQ + 1];

    // Load q,k,v: 3*16*64 floats = 768 float4, 6 per thread.
    #pragma unroll
    for (int l = 0; l < 6; l++) {
        int e   = tid + l * 128;
        int sel = e >> 8;          // 0=q 1=k 2=v
        int rem = e & 255;
        int s   = rem >> 4;
        int d   = (rem & 15) * 4;
        float4 v = *reinterpret_cast<const float4*>(
            &g_qkv[(base + s) * NQKV + sel * HIDDEN + h * HEAD_DIM + d]);
        float* dst = (sel == 0) ? &sq[s][d] : (sel == 1) ? &sk[s][d] : &sv[s][d];
        *reinterpret_cast<float4*>(dst) = v;
    }
    __syncthreads();

    // scores[i][j] = (q_i . k_j) / 8   (256 scores, 2 per thread)
    #pragma unroll
    for (int l = 0; l < 2; l++) {
        int sidx = tid + l * 128;
        int i = sidx >> 4, j = sidx & 15;
        float a = 0.f;
        #pragma unroll
        for (int d = 0; d < HEAD_DIM; d++) a += sq[i][d] * sk[j][d];
        sp[i][j] = a * 0.125f;
    }
    __syncthreads();

    // softmax per row (16 threads)
    if (tid < SEQ) {
        float m = sp[tid][0];
        #pragma unroll
        for (int j = 1; j < SEQ; j++) m = fmaxf(m, sp[tid][j]);
        float e[SEQ], s = 0.f;
        #pragma unroll
        for (int j = 0; j < SEQ; j++) { e[j] = expf(sp[tid][j] - m); s += e[j]; }
        float inv = 1.0f / s;
        #pragma unroll
        for (int j = 0; j < SEQ; j++) sp[tid][j] = e[j] * inv;
    }
    __syncthreads();

    // out[i][d] = sum_j p[i][j] * v[j][d]   (1024 outputs, 8 per thread)
    #pragma unroll
    for (int l = 0; l < 8; l++) {
        int o = tid + l * 128;
        int i = o >> 6, d = o & 63;
        float a = 0.f;
        #pragma unroll
        for (int j = 0; j < SEQ; j++) a += sp[i][j] * sv[j][d];
        g_attn[(base + i) * HIDDEN + h * HEAD_DIM + d] = __float2half(a);
    }
}

// ---------------------------------------------------------------------------
extern "C" void kernel_launch(void* const* d_in, const int* in_sizes, int n_in,
                              void* d_out, int out_size) {
    const float* x    = (const float*)d_in[0];   // [4096,16,512]
    const float* wqkv = (const float*)d_in[1];   // [1536,512]
    const float* wo   = (const float*)d_in[2];   // [512,512]
    float* out        = (float*)d_out;           // [4096,16,512]

    f2h_x_kernel <<<(NTOK * HIDDEN) / 1024, 256>>>(x);
    f2h_wq_kernel<<<(NQKV * HIDDEN) / 1024, 256>>>(wqkv);
    f2h_wo_kernel<<<(HIDDEN * HIDDEN) / 1024, 256>>>(wo);

    {   // QKV: [65536,512] x [512,1536]
        dim3 grid(NQKV / 128, NTOK / 128);
        gemm_qkv_kernel<<<grid, 256>>>();
    }

    attn_kernel<<<BATCH * HEADS, 128>>>();

    {   // O-proj: [65536,512] x [512,512]
        dim3 grid(HIDDEN / 128, NTOK / 128);
        gemm_out_kernel<<<grid, 256>>>(out);
    }
}

// round 3
// speedup vs baseline: 1.1696x; 1.1696x over previous
#include <cuda_runtime.h>
#include <cuda_fp16.h>
#include <mma.h>
#include <cstdint>

using namespace nvcuda;

#define HIDDEN   512
#define HEADS    8
#define HEAD_DIM 64
#define BATCH    4096
#define SEQ      16
#define NTOK     (BATCH * SEQ)   // 65536
#define NQKV     (3 * HIDDEN)    // 1536

// ---- scratch (no allocs allowed; device globals are the sanctioned path) ----
__device__ __half g_xh  [(size_t)NTOK * HIDDEN];   // 64 MiB  fp16 input
__device__ __half g_wq  [(size_t)NQKV * HIDDEN];   // 1.5 MiB fp16 w_qkv
__device__ __half g_wo  [(size_t)HIDDEN * HIDDEN]; // 0.5 MiB fp16 w_o
__device__ __half g_qkvh[(size_t)NTOK * NQKV];     // 192 MiB fp16 qkv
__device__ __half g_attn[(size_t)NTOK * HIDDEN];   // 64 MiB  fp16 attn out

// ---------------------------------------------------------------------------
// cp.async helpers (LDGSTS, 16B)
// ---------------------------------------------------------------------------
__device__ __forceinline__ void cp_async16(void* smem, const void* gmem) {
    unsigned int s = (unsigned int)__cvta_generic_to_shared(smem);
    asm volatile("cp.async.cg.shared.global [%0], [%1], 16;\n" :: "r"(s), "l"(gmem));
}
__device__ __forceinline__ void cp_commit() {
    asm volatile("cp.async.commit_group;\n" ::: "memory");
}
template <int N>
__device__ __forceinline__ void cp_wait() {
    asm volatile("cp.async.wait_group %0;\n" :: "n"(N) : "memory");
}

// ---------------------------------------------------------------------------
// fp32 -> fp16 converters (n always multiple of 4)
// ---------------------------------------------------------------------------
__device__ __forceinline__ void f2h_body(const float* __restrict__ in,
                                         __half* __restrict__ out, int n) {
    int i = 4 * (blockIdx.x * blockDim.x + threadIdx.x);
    if (i < n) {
        float4 v = *reinterpret_cast<const float4*>(in + i);
        *reinterpret_cast<__half2*>(out + i)     = __floats2half2_rn(v.x, v.y);
        *reinterpret_cast<__half2*>(out + i + 2) = __floats2half2_rn(v.z, v.w);
    }
}

__global__ void f2h_x_kernel (const float* __restrict__ in) { f2h_body(in, g_xh, NTOK * HIDDEN); }
__global__ void f2h_wq_kernel(const float* __restrict__ in) { f2h_body(in, g_wq, NQKV * HIDDEN); }
__global__ void f2h_wo_kernel(const float* __restrict__ in) { f2h_body(in, g_wo, HIDDEN * HIDDEN); }

// ---------------------------------------------------------------------------
// GEMM: C[M,N] = A[M,K] * B[N,K]^T   (A,B fp16 K-contiguous; fp32 accum)
// Block tile 128x128x32, 256 threads, 8 warps -> warp tile 32x64.
// 2-stage cp.async double buffering: one __syncthreads per K-step, global
// loads for stage s+1 overlap MMA on stage s.
// HALF_OUT selects fp16 (epilogue convert) vs fp32 output.
// ---------------------------------------------------------------------------
template <bool HALF_OUT>
__device__ __forceinline__ void gemm_body(const __half* __restrict__ A,
                                          const __half* __restrict__ B,
                                          __half* __restrict__ Ch,
                                          float* __restrict__ Cf,
                                          int N, int K) {
    constexpr int BM = 128, BN = 128, BK = 32, LDS = BK + 8; // 40 halves = 80B rows
    __shared__ __align__(16) __half As[2][BM * LDS];
    __shared__ __align__(16) __half Bs[2][BN * LDS];

    const int bm   = blockIdx.y * BM;
    const int bn   = blockIdx.x * BN;
    const int tid  = threadIdx.x;
    const int warp = tid >> 5;
    const int wm   = (warp & 3) * 32;   // warp row offset in tile
    const int wn   = (warp >> 2) * 64;  // warp col offset in tile

    // stage loader: 128x32 halves of A and B = 512 int4 each, 2/thread each
    auto stage_load = [&](int kt, int buf) {
        #pragma unroll
        for (int l = 0; l < 2; l++) {
            int v  = tid + l * 256;
            int r  = v >> 2;
            int c8 = (v & 3) * 8;
            cp_async16(&As[buf][r * LDS + c8], &A[(size_t)(bm + r) * K + kt + c8]);
            cp_async16(&Bs[buf][r * LDS + c8], &B[(size_t)(bn + r) * K + kt + c8]);
        }
        cp_commit();
    };

    wmma::fragment<wmma::accumulator, 16, 16, 16, float> acc[2][4];
    #pragma unroll
    for (int i = 0; i < 2; i++)
        #pragma unroll
        for (int j = 0; j < 4; j++) wmma::fill_fragment(acc[i][j], 0.0f);

    const int nst = K / BK;
    stage_load(0, 0);

    for (int s = 0; s < nst; s++) {
        cp_wait<0>();
        __syncthreads();               // stage s visible to all warps
        if (s + 1 < nst) stage_load((s + 1) * BK, (s + 1) & 1);  // overlaps MMA

        const __half* as = As[s & 1];
        const __half* bs = Bs[s & 1];
        #pragma unroll
        for (int kk = 0; kk < BK; kk += 16) {
            wmma::fragment<wmma::matrix_a, 16, 16, 16, __half, wmma::row_major> af[2];
            wmma::fragment<wmma::matrix_b, 16, 16, 16, __half, wmma::col_major> bf[4];
            #pragma unroll
            for (int i = 0; i < 2; i++)
                wmma::load_matrix_sync(af[i], &as[(wm + i * 16) * LDS + kk], LDS);
            #pragma unroll
            for (int j = 0; j < 4; j++)
                wmma::load_matrix_sync(bf[j], &bs[(wn + j * 16) * LDS + kk], LDS);
            #pragma unroll
            for (int i = 0; i < 2; i++)
                #pragma unroll
                for (int j = 0; j < 4; j++)
                    wmma::mma_sync(acc[i][j], af[i], bf[j], acc[i][j]);
        }
        // no bottom sync needed: next iteration's top sync orders this stage's
        // reads before stage s+2's cp.async writes reuse this buffer
    }

    #pragma unroll
    for (int i = 0; i < 2; i++) {
        #pragma unroll
        for (int j = 0; j < 4; j++) {
            if (HALF_OUT) {
                wmma::fragment<wmma::accumulator, 16, 16, 16, __half> hf;
                #pragma unroll
                for (int e = 0; e < hf.num_elements; e++)
                    hf.x[e] = __float2half(acc[i][j].x[e]);
                wmma::store_matrix_sync(&Ch[(size_t)(bm + wm + i * 16) * N + bn + wn + j * 16],
                                        hf, N, wmma::mem_row_major);
            } else {
                wmma::store_matrix_sync(&Cf[(size_t)(bm + wm + i * 16) * N + bn + wn + j * 16],
                                        acc[i][j], N, wmma::mem_row_major);
            }
        }
    }
}

__global__ __launch_bounds__(256) void gemm_qkv_kernel() {
    gemm_body<true>(g_xh, g_wq, g_qkvh, nullptr, NQKV, HIDDEN);
}
__global__ __launch_bounds__(256) void gemm_out_kernel(float* __restrict__ C) {
    gemm_body<false>(g_attn, g_wo, nullptr, C, HIDDEN, HIDDEN);
}

// ---------------------------------------------------------------------------
// Attention: one block per (batch, head). fp16 qkv in, exact fp32 softmax,
// fp16 attn out in [token, h*64+d] layout.
// ---------------------------------------------------------------------------
__global__ __launch_bounds__(128) void attn_kernel() {
    const int b = blockIdx.x >> 3;
    const int h = blockIdx.x & 7;
    const size_t base = (size_t)b * SEQ;
    const int tid = threadIdx.x;

    __shared__ float sq[SEQ][68], sk[SEQ][68], sv[SEQ][68]; // pad vs bank conflicts
    __shared__ float sp[SEQ][SEQ + 1];

    // Load q,k,v: 3*16*64 halves = 384 int4 (8 halves each), 3 per thread.
    #pragma unroll
    for (int l = 0; l < 3; l++) {
        int s  = tid >> 3;
        int d8 = (tid & 7) * 8;
        int4 raw = *reinterpret_cast<const int4*>(
            &g_qkvh[(base + s) * NQKV + l * HIDDEN + h * HEAD_DIM + d8]);
        const __half2* hp = reinterpret_cast<const __half2*>(&raw);
        float* dst = (l == 0) ? &sq[s][d8] : (l == 1) ? &sk[s][d8] : &sv[s][d8];
        #pragma unroll
        for (int p = 0; p < 4; p++) {
            float2 f = __half22float2(hp[p]);
            dst[2 * p]     = f.x;
            dst[2 * p + 1] = f.y;
        }
    }
    __syncthreads();

    // scores[i][j] = (q_i . k_j) / 8   (256 scores, 2 per thread)
    #pragma unroll
    for (int l = 0; l < 2; l++) {
        int sidx = tid + l * 128;
        int i = sidx >> 4, j = sidx & 15;
        float a = 0.f;
        #pragma unroll
        for (int d = 0; d < HEAD_DIM; d++) a += sq[i][d] * sk[j][d];
        sp[i][j] = a * 0.125f;
    }
    __syncthreads();

    // softmax per row (16 threads)
    if (tid < SEQ) {
        float m = sp[tid][0];
        #pragma unroll
        for (int j = 1; j < SEQ; j++) m = fmaxf(m, sp[tid][j]);
        float e[SEQ], s = 0.f;
        #pragma unroll
        for (int j = 0; j < SEQ; j++) { e[j] = expf(sp[tid][j] - m); s += e[j]; }
        float inv = 1.0f / s;
        #pragma unroll
        for (int j = 0; j < SEQ; j++) sp[tid][j] = e[j] * inv;
    }
    __syncthreads();

    // out[i][d] = sum_j p[i][j] * v[j][d]   (512 half2 outputs, 4 per thread)
    #pragma unroll
    for (int l = 0; l < 4; l++) {
        int o  = tid + l * 128;          // 0..511, indexes pairs
        int i  = o >> 5;                 // row 0..15
        int d2 = (o & 31) * 2;           // pair base 0..62
        float a0 = 0.f, a1 = 0.f;
        #pragma unroll
        for (int j = 0; j < SEQ; j++) {
            float p = sp[i][j];
            a0 += p * sv[j][d2];
            a1 += p * sv[j][d2 + 1];
        }
        *reinterpret_cast<__half2*>(&g_attn[(base + i) * HIDDEN + h * HEAD_DIM + d2]) =
            __floats2half2_rn(a0, a1);
    }
}

// ---------------------------------------------------------------------------
extern "C" void kernel_launch(void* const* d_in, const int* in_sizes, int n_in,
                              void* d_out, int out_size) {
    const float* x    = (const float*)d_in[0];   // [4096,16,512]
    const float* wqkv = (const float*)d_in[1];   // [1536,512]
    const float* wo   = (const float*)d_in[2];   // [512,512]
    float* out        = (float*)d_out;           // [4096,16,512]

    f2h_x_kernel <<<(NTOK * HIDDEN) / 1024, 256>>>(x);
    f2h_wq_kernel<<<(NQKV * HIDDEN) / 1024, 256>>>(wqkv);
    f2h_wo_kernel<<<(HIDDEN * HIDDEN) / 1024, 256>>>(wo);

    {   // QKV: [65536,512] x [512,1536]
        dim3 grid(NQKV / 128, NTOK / 128);
        gemm_qkv_kernel<<<grid, 256>>>();
    }

    attn_kernel<<<BATCH * HEADS, 128>>>();

    {   // O-proj: [65536,512] x [512,512]
        dim3 grid(HIDDEN / 128, NTOK / 128);
        gemm_out_kernel<<<grid, 256>>>(out);
    }
}

// round 7
// speedup vs baseline: 1.2362x; 1.0570x over previous
#include <cuda_runtime.h>
#include <cuda_fp16.h>
#include <mma.h>
#include <cstdint>

using namespace nvcuda;

#define HIDDEN   512
#define HEADS    8
#define HEAD_DIM 64
#define BATCH    4096
#define SEQ      16
#define NTOK     (BATCH * SEQ)   // 65536
#define NQKV     (3 * HIDDEN)    // 1536

// ---- scratch (no allocs allowed; device globals are the sanctioned path) ----
__device__ __half g_xh  [(size_t)NTOK * HIDDEN];   // 64 MiB  fp16 input
__device__ __half g_wq  [(size_t)NQKV * HIDDEN];   // 1.5 MiB fp16 w_qkv
__device__ __half g_wo  [(size_t)HIDDEN * HIDDEN]; // 0.5 MiB fp16 w_o
__device__ __half g_qkvh[(size_t)NTOK * NQKV];     // 192 MiB fp16 qkv
__device__ __half g_attn[(size_t)NTOK * HIDDEN];   // 64 MiB  fp16 attn out

// ---------------------------------------------------------------------------
// cp.async helpers (LDGSTS, 16B)
// ---------------------------------------------------------------------------
__device__ __forceinline__ void cp_async16(void* smem, const void* gmem) {
    unsigned int s = (unsigned int)__cvta_generic_to_shared(smem);
    asm volatile("cp.async.cg.shared.global [%0], [%1], 16;\n" :: "r"(s), "l"(gmem));
}
__device__ __forceinline__ void cp_commit() {
    asm volatile("cp.async.commit_group;\n" ::: "memory");
}
template <int N>
__device__ __forceinline__ void cp_wait() {
    asm volatile("cp.async.wait_group %0;\n" :: "n"(N) : "memory");
}

// ---------------------------------------------------------------------------
// fp32 -> fp16 converters (n always multiple of 4)
// ---------------------------------------------------------------------------
__device__ __forceinline__ void f2h_body(const float* __restrict__ in,
                                         __half* __restrict__ out, int n) {
    int i = 4 * (blockIdx.x * blockDim.x + threadIdx.x);
    if (i < n) {
        float4 v = *reinterpret_cast<const float4*>(in + i);
        *reinterpret_cast<__half2*>(out + i)     = __floats2half2_rn(v.x, v.y);
        *reinterpret_cast<__half2*>(out + i + 2) = __floats2half2_rn(v.z, v.w);
    }
}
__global__ void f2h_x_kernel (const float* __restrict__ in) { f2h_body(in, g_xh, NTOK * HIDDEN); }
__global__ void f2h_wq_kernel(const float* __restrict__ in) { f2h_body(in, g_wq, NQKV * HIDDEN); }
__global__ void f2h_wo_kernel(const float* __restrict__ in) { f2h_body(in, g_wo, HIDDEN * HIDDEN); }

// ---------------------------------------------------------------------------
// GEMM: C[M,N] = A[M,K] * B[N,K]^T   (A,B fp16 K-contiguous; fp32 accum)
// CTA tile 128x128x32, 128 threads = 4 warps, warp tile 64x64 (2x2 grid).
// 2-stage cp.async double buffering (identical skeleton to the passing
// Round-3 kernel; only thread count / warp tiling changed). Static smem.
// ---------------------------------------------------------------------------
template <bool HALF_OUT>
__device__ __forceinline__ void gemm_body(const __half* __restrict__ A,
                                          const __half* __restrict__ B,
                                          __half* __restrict__ Ch,
                                          float* __restrict__ Cf,
                                          int N, int K) {
    constexpr int BM = 128, BN = 128, BK = 32, LDS = BK + 8; // 40 halves = 80B rows
    __shared__ __align__(16) __half As[2][BM * LDS];
    __shared__ __align__(16) __half Bs[2][BN * LDS];

    const int bm   = blockIdx.y * BM;
    const int bn   = blockIdx.x * BN;
    const int tid  = threadIdx.x;
    const int warp = tid >> 5;
    const int wm   = (warp & 1) * 64;    // warp row offset in tile
    const int wn   = (warp >> 1) * 64;   // warp col offset in tile

    // stage loader: 128x32 halves of A and B = 512 int4 each, 4/thread each
    auto stage_load = [&](int kt, int buf) {
        #pragma unroll
        for (int l = 0; l < 4; l++) {
            int v  = tid + l * 128;
            int r  = v >> 2;
            int c8 = (v & 3) * 8;
            cp_async16(&As[buf][r * LDS + c8], &A[(size_t)(bm + r) * K + kt + c8]);
            cp_async16(&Bs[buf][r * LDS + c8], &B[(size_t)(bn + r) * K + kt + c8]);
        }
        cp_commit();
    };

    wmma::fragment<wmma::accumulator, 16, 16, 16, float> acc[4][4];
    #pragma unroll
    for (int i = 0; i < 4; i++)
        #pragma unroll
        for (int j = 0; j < 4; j++) wmma::fill_fragment(acc[i][j], 0.0f);

    const int nst = K / BK;
    stage_load(0, 0);

    for (int s = 0; s < nst; s++) {
        cp_wait<0>();
        __syncthreads();               // stage s visible to all warps
        if (s + 1 < nst) stage_load((s + 1) * BK, (s + 1) & 1);  // overlaps MMA

        const __half* as = As[s & 1];
        const __half* bs = Bs[s & 1];
        #pragma unroll
        for (int kk = 0; kk < BK; kk += 16) {
            wmma::fragment<wmma::matrix_a, 16, 16, 16, __half, wmma::row_major> af[4];
            wmma::fragment<wmma::matrix_b, 16, 16, 16, __half, wmma::col_major> bf[4];
            #pragma unroll
            for (int i = 0; i < 4; i++)
                wmma::load_matrix_sync(af[i], &as[(wm + i * 16) * LDS + kk], LDS);
            #pragma unroll
            for (int j = 0; j < 4; j++)
                wmma::load_matrix_sync(bf[j], &bs[(wn + j * 16) * LDS + kk], LDS);
            #pragma unroll
            for (int i = 0; i < 4; i++)
                #pragma unroll
                for (int j = 0; j < 4; j++)
                    wmma::mma_sync(acc[i][j], af[i], bf[j], acc[i][j]);
        }
        // next iteration's top sync orders this stage's reads before the
        // buffer is overwritten two stages later
    }

    #pragma unroll
    for (int i = 0; i < 4; i++) {
        #pragma unroll
        for (int j = 0; j < 4; j++) {
            if (HALF_OUT) {
                wmma::fragment<wmma::accumulator, 16, 16, 16, __half> hf;
                #pragma unroll
                for (int e = 0; e < hf.num_elements; e++)
                    hf.x[e] = __float2half(acc[i][j].x[e]);
                wmma::store_matrix_sync(&Ch[(size_t)(bm + wm + i * 16) * N + bn + wn + j * 16],
                                        hf, N, wmma::mem_row_major);
            } else {
                wmma::store_matrix_sync(&Cf[(size_t)(bm + wm + i * 16) * N + bn + wn + j * 16],
                                        acc[i][j], N, wmma::mem_row_major);
            }
        }
    }
}

__global__ __launch_bounds__(128) void gemm_qkv_kernel() {
    gemm_body<true>(g_xh, g_wq, g_qkvh, nullptr, NQKV, HIDDEN);
}
__global__ __launch_bounds__(128) void gemm_out_kernel(float* __restrict__ C) {
    gemm_body<false>(g_attn, g_wo, nullptr, C, HIDDEN, HIDDEN);
}

// ---------------------------------------------------------------------------
// Attention: one block per (batch, head). fp16 qkv in, exact fp32 softmax,
// fp16 attn out in [token, h*64+d] layout.
// ---------------------------------------------------------------------------
__global__ __launch_bounds__(128) void attn_kernel() {
    const int b = blockIdx.x >> 3;
    const int h = blockIdx.x & 7;
    const size_t base = (size_t)b * SEQ;
    const int tid = threadIdx.x;

    __shared__ float sq[SEQ][68], sk[SEQ][68], sv[SEQ][68];
    __shared__ float sp[SEQ][SEQ + 1];

    #pragma unroll
    for (int l = 0; l < 3; l++) {
        int s  = tid >> 3;
        int d8 = (tid & 7) * 8;
        int4 raw = *reinterpret_cast<const int4*>(
            &g_qkvh[(base + s) * NQKV + l * HIDDEN + h * HEAD_DIM + d8]);
        const __half2* hp = reinterpret_cast<const __half2*>(&raw);
        float* dst = (l == 0) ? &sq[s][d8] : (l == 1) ? &sk[s][d8] : &sv[s][d8];
        #pragma unroll
        for (int p = 0; p < 4; p++) {
            float2 f = __half22float2(hp[p]);
            dst[2 * p]     = f.x;
            dst[2 * p + 1] = f.y;
        }
    }
    __syncthreads();

    #pragma unroll
    for (int l = 0; l < 2; l++) {
        int sidx = tid + l * 128;
        int i = sidx >> 4, j = sidx & 15;
        float a = 0.f;
        #pragma unroll
        for (int d = 0; d < HEAD_DIM; d++) a += sq[i][d] * sk[j][d];
        sp[i][j] = a * 0.125f;
    }
    __syncthreads();

    if (tid < SEQ) {
        float m = sp[tid][0];
        #pragma unroll
        for (int j = 1; j < SEQ; j++) m = fmaxf(m, sp[tid][j]);
        float e[SEQ], s = 0.f;
        #pragma unroll
        for (int j = 0; j < SEQ; j++) { e[j] = expf(sp[tid][j] - m); s += e[j]; }
        float inv = 1.0f / s;
        #pragma unroll
        for (int j = 0; j < SEQ; j++) sp[tid][j] = e[j] * inv;
    }
    __syncthreads();

    #pragma unroll
    for (int l = 0; l < 4; l++) {
        int o  = tid + l * 128;
        int i  = o >> 5;
        int d2 = (o & 31) * 2;
        float a0 = 0.f, a1 = 0.f;
        #pragma unroll
        for (int j = 0; j < SEQ; j++) {
            float p = sp[i][j];
            a0 += p * sv[j][d2];
            a1 += p * sv[j][d2 + 1];
        }
        *reinterpret_cast<__half2*>(&g_attn[(base + i) * HIDDEN + h * HEAD_DIM + d2]) =
            __floats2half2_rn(a0, a1);
    }
}

// ---------------------------------------------------------------------------
extern "C" void kernel_launch(void* const* d_in, const int* in_sizes, int n_in,
                              void* d_out, int out_size) {
    const float* x    = (const float*)d_in[0];   // [4096,16,512]
    const float* wqkv = (const float*)d_in[1];   // [1536,512]
    const float* wo   = (const float*)d_in[2];   // [512,512]
    float* out        = (float*)d_out;           // [4096,16,512]

    f2h_x_kernel <<<(NTOK * HIDDEN) / 1024, 256>>>(x);
    f2h_wq_kernel<<<(NQKV * HIDDEN) / 1024, 256>>>(wqkv);
    f2h_wo_kernel<<<(HIDDEN * HIDDEN) / 1024, 256>>>(wo);

    {   // QKV: [65536,512] x [512,1536]
        dim3 grid(NQKV / 128, NTOK / 128);
        gemm_qkv_kernel<<<grid, 128>>>();
    }

    attn_kernel<<<BATCH * HEADS, 128>>>();

    {   // O-proj: [65536,512] x [512,512]
        dim3 grid(HIDDEN / 128, NTOK / 128);
        gemm_out_kernel<<<grid, 128>>>(out);
    }
}